// round 3
// baseline (speedup 1.0000x reference)
#include <cuda_runtime.h>
#include <math.h>

#define NN 32768
#define EE 262144
#define DD 256
#define HH 4
#define GG 32
#define BN_EPS 1e-5f

// ------------------------- scratch (device globals) -------------------------
__device__ float g_h[NN * DD];
__device__ float g_q[NN * DD];
__device__ float g_k[NN * DD];
__device__ float g_v[NN * DD];
__device__ float g_xr[NN * DD];
__device__ float g_msg[NN * DD];      // attention aggregate "out"
__device__ float g_exw[EE * HH];      // exp(alpha) per edge per head
__device__ float g_den[NN * HH];      // softmax denominators per dst node/head
__device__ float g_colstats[2 * DD];  // [0..255] colsum, [256..511] colsumsq
__device__ float g_gate[NN];          // exp(gate) per node
__device__ float g_gden[GG];          // per-graph softmax denom
__device__ float g_hG[GG * DD];       // pooled per-graph embedding

// ------------------------- zero kernels -------------------------
__global__ void zero_layer_kernel() {
    int i = blockIdx.x * blockDim.x + threadIdx.x;
    if (i < NN * DD) g_msg[i] = 0.f;
    if (i < NN * HH) g_den[i] = 0.f;
    if (i < 2 * DD) g_colstats[i] = 0.f;
}

__global__ void zero_readout_kernel() {
    int i = blockIdx.x * blockDim.x + threadIdx.x;
    if (i < GG * DD) g_hG[i] = 0.f;
    if (i < GG) g_gden[i] = 0.f;
}

// ------------------------- encoder: h = x @ enc_W + enc_b -------------------------
__global__ void encoder_kernel(const float* __restrict__ x,
                               const float* __restrict__ W,
                               const float* __restrict__ b) {
    int i = blockIdx.x * blockDim.x + threadIdx.x;
    if (i >= NN * DD) return;
    int n = i >> 8, d = i & 255;
    g_h[i] = x[n * 2] * W[d] + x[n * 2 + 1] * W[DD + d] + b[d];
}

// ------------------------- SGEMM: C = g_h[NNx256] @ B[256x256] + bias -------------------------
// BM=128, BN=128, BK=8, 256 threads, 8x8 register microtile per thread.
__global__ __launch_bounds__(256) void sgemm_bias(const float* __restrict__ B,
                                                  const float* __restrict__ bias,
                                                  int outsel) {
    __shared__ float As[8][136];  // transposed A tile, padded
    __shared__ float Bs[8][128];

    float* Cm = (outsel == 0) ? g_q : (outsel == 1) ? g_k : (outsel == 2) ? g_v : g_xr;
    const float* A = g_h;

    int tid = threadIdx.x;
    int bm = blockIdx.y * 128;
    int bn = blockIdx.x * 128;
    int tx = tid & 15, ty = tid >> 4;

    int am = tid >> 1;           // 0..127 : A tile row
    int af = (tid & 1) * 4;      // 0 or 4 : A tile k-offset
    int bk = tid >> 5;           // 0..7   : B tile row
    int bc = (tid & 31) * 4;     // 0..124 : B tile col

    float acc[8][8];
#pragma unroll
    for (int i = 0; i < 8; i++)
#pragma unroll
        for (int j = 0; j < 8; j++) acc[i][j] = 0.f;

    for (int k0 = 0; k0 < 256; k0 += 8) {
        float4 av = *reinterpret_cast<const float4*>(&A[(bm + am) * 256 + k0 + af]);
        As[af + 0][am] = av.x;
        As[af + 1][am] = av.y;
        As[af + 2][am] = av.z;
        As[af + 3][am] = av.w;
        float4 bv = *reinterpret_cast<const float4*>(&B[(k0 + bk) * 256 + bn + bc]);
        *reinterpret_cast<float4*>(&Bs[bk][bc]) = bv;
        __syncthreads();
#pragma unroll
        for (int kk = 0; kk < 8; kk++) {
            float a[8], b[8];
#pragma unroll
            for (int i = 0; i < 8; i += 4) {
                float4 t = *reinterpret_cast<float4*>(&As[kk][ty * 8 + i]);
                a[i] = t.x; a[i + 1] = t.y; a[i + 2] = t.z; a[i + 3] = t.w;
            }
#pragma unroll
            for (int j = 0; j < 8; j += 4) {
                float4 t = *reinterpret_cast<float4*>(&Bs[kk][tx * 8 + j]);
                b[j] = t.x; b[j + 1] = t.y; b[j + 2] = t.z; b[j + 3] = t.w;
            }
#pragma unroll
            for (int i = 0; i < 8; i++)
#pragma unroll
                for (int j = 0; j < 8; j++) acc[i][j] += a[i] * b[j];
        }
        __syncthreads();
    }
#pragma unroll
    for (int i = 0; i < 8; i++) {
        int row = bm + ty * 8 + i;
#pragma unroll
        for (int j = 0; j < 8; j += 4) {
            int col = bn + tx * 8 + j;
            float4 o;
            o.x = acc[i][j + 0] + bias[col + 0];
            o.y = acc[i][j + 1] + bias[col + 1];
            o.z = acc[i][j + 2] + bias[col + 2];
            o.w = acc[i][j + 3] + bias[col + 3];
            *reinterpret_cast<float4*>(&Cm[row * 256 + col]) = o;
        }
    }
}

// ------------------------- edge pass 1: alpha + exp + denom -------------------------
// warp per edge; lane l covers channels [8l, 8l+8) -> heads are lane groups of 8.
__global__ void edge_alpha_kernel(const int* __restrict__ src, const int* __restrict__ dst,
                                  const float* __restrict__ ea, const float* __restrict__ We) {
    __shared__ float sWe[256];
    int tid = threadIdx.x;
    sWe[tid] = We[tid];
    __syncthreads();
    int warp = tid >> 5, lane = tid & 31;
    int e = blockIdx.x * 8 + warp;
    if (e >= EE) return;
    int s = src[e], d = dst[e];
    float av = ea[e];
    int head = lane >> 3, sub = lane & 7;
    int ch = head * 64 + sub * 8;
    const float4* qp = reinterpret_cast<const float4*>(&g_q[d * 256 + ch]);
    const float4* kp = reinterpret_cast<const float4*>(&g_k[s * 256 + ch]);
    const float4* wp = reinterpret_cast<const float4*>(&sWe[ch]);
    float p = 0.f;
#pragma unroll
    for (int t = 0; t < 2; t++) {
        float4 q4 = qp[t], k4 = kp[t], w4 = wp[t];
        p += q4.x * (k4.x + av * w4.x) + q4.y * (k4.y + av * w4.y) +
             q4.z * (k4.z + av * w4.z) + q4.w * (k4.w + av * w4.w);
    }
    p += __shfl_down_sync(0xffffffffu, p, 4);
    p += __shfl_down_sync(0xffffffffu, p, 2);
    p += __shfl_down_sync(0xffffffffu, p, 1);
    if (sub == 0) {
        float ex = expf(p * 0.125f);  // scale = 1/sqrt(64); softmax max-shift is a no-op on ratios
        g_exw[e * 4 + head] = ex;
        atomicAdd(&g_den[d * 4 + head], ex);
    }
}

// ------------------------- edge pass 2: weighted message scatter -------------------------
__global__ void edge_msg_kernel(const int* __restrict__ src, const int* __restrict__ dst,
                                const float* __restrict__ ea, const float* __restrict__ We) {
    __shared__ float sWe[256];
    int tid = threadIdx.x;
    sWe[tid] = We[tid];
    __syncthreads();
    int warp = tid >> 5, lane = tid & 31;
    int e = blockIdx.x * 8 + warp;
    if (e >= EE) return;
    int s = src[e], d = dst[e];
    float av = ea[e];
    int head = lane >> 3, sub = lane & 7;
    float w = g_exw[e * 4 + head] / g_den[d * 4 + head];
    int ch = head * 64 + sub * 8;
    const float4* vp = reinterpret_cast<const float4*>(&g_v[s * 256 + ch]);
    const float4* wp = reinterpret_cast<const float4*>(&sWe[ch]);
#pragma unroll
    for (int t = 0; t < 2; t++) {
        float4 v4 = vp[t], w4 = wp[t];
        float4 m;
        m.x = (v4.x + av * w4.x) * w;
        m.y = (v4.y + av * w4.y) * w;
        m.z = (v4.z + av * w4.z) * w;
        m.w = (v4.w + av * w4.w) * w;
        atomicAdd(reinterpret_cast<float4*>(&g_msg[d * 256 + ch + t * 4]), m);  // sm_90+ vector RED
    }
}

// ------------------------- beta-gated skip combine -------------------------
// warp per node: beta = sigmoid([out, x_r, out-x_r] . Wbeta); h = beta*x_r + (1-beta)*out
__global__ void combine_kernel(const float* __restrict__ Wb) {
    __shared__ float sWb[768];
    int tid = threadIdx.x;
    sWb[tid] = Wb[tid];
    sWb[tid + 256] = Wb[tid + 256];
    sWb[tid + 512] = Wb[tid + 512];
    __syncthreads();
    int warp = tid >> 5, lane = tid & 31;
    int n = blockIdx.x * 8 + warp;
    if (n >= NN) return;
    int ch = lane * 8;
    float4 o0 = *reinterpret_cast<const float4*>(&g_msg[n * 256 + ch]);
    float4 o1 = *reinterpret_cast<const float4*>(&g_msg[n * 256 + ch + 4]);
    float4 x0 = *reinterpret_cast<const float4*>(&g_xr[n * 256 + ch]);
    float4 x1 = *reinterpret_cast<const float4*>(&g_xr[n * 256 + ch + 4]);
    float ov[8] = {o0.x, o0.y, o0.z, o0.w, o1.x, o1.y, o1.z, o1.w};
    float xv[8] = {x0.x, x0.y, x0.z, x0.w, x1.x, x1.y, x1.z, x1.w};
    float p = 0.f;
#pragma unroll
    for (int i = 0; i < 8; i++)
        p += ov[i] * sWb[ch + i] + xv[i] * sWb[256 + ch + i] + (ov[i] - xv[i]) * sWb[512 + ch + i];
#pragma unroll
    for (int off = 16; off; off >>= 1) p += __shfl_xor_sync(0xffffffffu, p, off);
    float beta = 1.f / (1.f + expf(-p));
    float r[8];
#pragma unroll
    for (int i = 0; i < 8; i++) r[i] = beta * xv[i] + (1.f - beta) * ov[i];
    *reinterpret_cast<float4*>(&g_h[n * 256 + ch]) = make_float4(r[0], r[1], r[2], r[3]);
    *reinterpret_cast<float4*>(&g_h[n * 256 + ch + 4]) = make_float4(r[4], r[5], r[6], r[7]);
}

// ------------------------- batchnorm column stats -------------------------
// 256 blocks x 256 threads; block b reduces rows [128b, 128b+128), thread t = column t.
__global__ void bn_reduce_kernel() {
    int d = threadIdx.x;
    int r0 = blockIdx.x * 128;
    float s = 0.f, s2 = 0.f;
    for (int r = 0; r < 128; r++) {
        float v = g_h[(r0 + r) * 256 + d];
        s += v;
        s2 += v * v;
    }
    atomicAdd(&g_colstats[d], s);
    atomicAdd(&g_colstats[256 + d], s2);
}

// ------------------------- BN apply + ELU -------------------------
__global__ void bn_apply_kernel(const float* __restrict__ gamma, const float* __restrict__ beta) {
    int i = blockIdx.x * blockDim.x + threadIdx.x;
    if (i >= NN * DD) return;
    int d = i & 255;
    float mu = g_colstats[d] * (1.f / NN);
    float var = g_colstats[256 + d] * (1.f / NN) - mu * mu;
    float y = gamma[d] * (g_h[i] - mu) * rsqrtf(var + BN_EPS) + beta[d];
    g_h[i] = y > 0.f ? y : expm1f(y);
}

// ------------------------- readout: gate softmax denom -------------------------
__global__ void gate_kernel(const int* __restrict__ batch, const float* __restrict__ gW,
                            const float* __restrict__ gb) {
    int tid = threadIdx.x;
    int warp = tid >> 5, lane = tid & 31;
    int n = blockIdx.x * 8 + warp;
    if (n >= NN) return;
    float p = 0.f;
#pragma unroll
    for (int t = 0; t < 8; t++) {
        int ch = lane + t * 32;
        p += g_h[n * 256 + ch] * gW[ch];
    }
#pragma unroll
    for (int off = 16; off; off >>= 1) p += __shfl_xor_sync(0xffffffffu, p, off);
    if (lane == 0) {
        float ex = expf(p + gb[0]);
        g_gate[n] = ex;
        atomicAdd(&g_gden[batch[n]], ex);
    }
}

// ------------------------- readout: weighted pooling -------------------------
__global__ void pool_kernel(const int* __restrict__ batch) {
    int i = blockIdx.x * blockDim.x + threadIdx.x;  // over NN*64 float4s
    if (i >= NN * 64) return;
    int n = i >> 6, c4 = (i & 63) * 4;
    int g = batch[n];
    float w = g_gate[n] / g_gden[g];
    float4 hv = *reinterpret_cast<const float4*>(&g_h[n * 256 + c4]);
    float4 m = make_float4(hv.x * w, hv.y * w, hv.z * w, hv.w * w);
    atomicAdd(reinterpret_cast<float4*>(&g_hG[g * 256 + c4]), m);
}

// ------------------------- decoder -------------------------
__global__ void final_kernel(const float* __restrict__ dW, const float* __restrict__ db,
                             const float* __restrict__ ob, float* __restrict__ out) {
    __shared__ float red[256];
    int g = blockIdx.x, t = threadIdx.x;
    red[t] = g_hG[g * 256 + t] * dW[t];
    __syncthreads();
    for (int s = 128; s > 0; s >>= 1) {
        if (t < s) red[t] += red[t + s];
        __syncthreads();
    }
    if (t == 0) out[g] = red[0] + db[0] + ob[0];
}

// ------------------------- launcher -------------------------
extern "C" void kernel_launch(void* const* d_in, const int* in_sizes, int n_in,
                              void* d_out, int out_size) {
    const float* x     = (const float*)d_in[0];
    const int*   ei    = (const int*)d_in[1];
    const float* ea    = (const float*)d_in[2];
    const int*   batch = (const int*)d_in[3];
    const float* encW  = (const float*)d_in[4];
    const float* encb  = (const float*)d_in[5];
    const float* Wq    = (const float*)d_in[6];
    const float* bq    = (const float*)d_in[7];
    const float* Wk    = (const float*)d_in[8];
    const float* bk    = (const float*)d_in[9];
    const float* Wv    = (const float*)d_in[10];
    const float* bv    = (const float*)d_in[11];
    const float* We    = (const float*)d_in[12];
    const float* Wskip = (const float*)d_in[13];
    const float* bskip = (const float*)d_in[14];
    const float* Wbeta = (const float*)d_in[15];
    const float* bng   = (const float*)d_in[16];
    const float* bnb   = (const float*)d_in[17];
    const float* gW    = (const float*)d_in[18];
    const float* gb    = (const float*)d_in[19];
    const float* dW    = (const float*)d_in[20];
    const float* db    = (const float*)d_in[21];
    const float* ob    = (const float*)d_in[22];
    float* out = (float*)d_out;

    const int* src = ei;        // edge_index[0]
    const int* dst = ei + EE;   // edge_index[1]

    const int TPB = 256;
    const int ND_BLOCKS = (NN * DD) / TPB;          // 32768
    dim3 gemm_grid(2, 256);

    encoder_kernel<<<ND_BLOCKS, TPB>>>(x, encW, encb);

    for (int l = 0; l < 2; l++) {
        const float* Wq_l = Wq + (size_t)l * DD * DD;
        const float* Wk_l = Wk + (size_t)l * DD * DD;
        const float* Wv_l = Wv + (size_t)l * DD * DD;
        const float* Ws_l = Wskip + (size_t)l * DD * DD;
        sgemm_bias<<<gemm_grid, TPB>>>(Wq_l, bq + l * DD, 0);
        sgemm_bias<<<gemm_grid, TPB>>>(Wk_l, bk + l * DD, 1);
        sgemm_bias<<<gemm_grid, TPB>>>(Wv_l, bv + l * DD, 2);
        sgemm_bias<<<gemm_grid, TPB>>>(Ws_l, bskip + l * DD, 3);

        zero_layer_kernel<<<ND_BLOCKS, TPB>>>();

        edge_alpha_kernel<<<EE / 8, TPB>>>(src, dst, ea, We + l * DD);
        edge_msg_kernel<<<EE / 8, TPB>>>(src, dst, ea, We + l * DD);

        combine_kernel<<<NN / 8, TPB>>>(Wbeta + l * 3 * DD);
        bn_reduce_kernel<<<256, TPB>>>();
        bn_apply_kernel<<<ND_BLOCKS, TPB>>>(bng + l * DD, bnb + l * DD);
    }

    zero_readout_kernel<<<32, TPB>>>();
    gate_kernel<<<NN / 8, TPB>>>(batch, gW, gb);
    pool_kernel<<<(NN * 64) / TPB, TPB>>>(batch);
    final_kernel<<<GG, TPB>>>(dW, db, ob, out);
}

// round 4
// speedup vs baseline: 1.7859x; 1.7859x over previous
#include <cuda_runtime.h>
#include <math.h>
#include <stdint.h>

#define NN 32768
#define EE 262144
#define DD 256
#define HH 4
#define GG 32
#define BN_EPS 1e-5f

// ------------------------- scratch (device globals) -------------------------
__device__ float g_h[NN * DD];
__device__ float g_q[NN * DD];
__device__ float g_k[NN * DD];
__device__ float g_v[NN * DD];
__device__ float g_xr[NN * DD];
__device__ float g_msg[NN * DD];      // attention aggregate "out"
__device__ float g_exw[EE * HH];      // exp(alpha) per edge per head
__device__ float g_den[NN * HH];      // softmax denominators per dst node/head
__device__ float g_colstats[2 * DD];  // [0..255] colsum, [256..511] colsumsq
__device__ float g_gate[NN];          // exp(gate) per node
__device__ float g_gden[GG];          // per-graph softmax denom
__device__ float g_hG[GG * DD];       // pooled per-graph embedding

// ------------------------- zero kernels -------------------------
__global__ void zero_layer_kernel() {
    int i = blockIdx.x * blockDim.x + threadIdx.x;
    if (i < NN * DD) g_msg[i] = 0.f;
    if (i < NN * HH) g_den[i] = 0.f;
    if (i < 2 * DD) g_colstats[i] = 0.f;
}

__global__ void zero_readout_kernel() {
    int i = blockIdx.x * blockDim.x + threadIdx.x;
    if (i < GG * DD) g_hG[i] = 0.f;
    if (i < GG) g_gden[i] = 0.f;
}

// ------------------------- encoder: h = x @ enc_W + enc_b -------------------------
__global__ void encoder_kernel(const float* __restrict__ x,
                               const float* __restrict__ W,
                               const float* __restrict__ b) {
    int i = blockIdx.x * blockDim.x + threadIdx.x;
    if (i >= NN * DD) return;
    int n = i >> 8, d = i & 255;
    g_h[i] = x[n * 2] * W[d] + x[n * 2 + 1] * W[DD + d] + b[d];
}

// ------------------------- TF32 tensor-core GEMM -------------------------
// C = g_h[32768x256] @ B[256x256] + bias, via mma.sync m16n8k8 tf32.
// BM=128, BN=128, BK=16; 8 warps (2 m x 4 n), warp tile 64x32.
#define SA 20    // A smem stride (floats): conflict-free for frag loads, 16B-aligned float4 slots
#define SB 136   // B smem stride (floats): conflict-free for frag loads

__device__ __forceinline__ uint32_t f2tf32(float f) {
    uint32_t r;
    asm("cvt.rna.tf32.f32 %0, %1;" : "=r"(r) : "f"(f));
    return r;
}

__device__ __forceinline__ void cp16(uint32_t s, const void* g) {
    asm volatile("cp.async.ca.shared.global [%0], [%1], 16;" :: "r"(s), "l"(g));
}

__device__ __forceinline__ void mma8(float* c, const uint32_t* a, const uint32_t* b) {
    asm volatile(
        "mma.sync.aligned.m16n8k8.row.col.f32.tf32.tf32.f32 "
        "{%0,%1,%2,%3}, {%4,%5,%6,%7}, {%8,%9}, {%0,%1,%2,%3};"
        : "+f"(c[0]), "+f"(c[1]), "+f"(c[2]), "+f"(c[3])
        : "r"(a[0]), "r"(a[1]), "r"(a[2]), "r"(a[3]), "r"(b[0]), "r"(b[1]));
}

__global__ __launch_bounds__(256, 2) void mma_gemm_bias(const float* __restrict__ B,
                                                        const float* __restrict__ bias,
                                                        int outsel) {
    __shared__ float As[2][128 * SA];
    __shared__ float Bs[2][16 * SB];

    float* Cm = (outsel == 0) ? g_q : (outsel == 1) ? g_k : (outsel == 2) ? g_v : g_xr;
    const float* A = g_h;

    int tid = threadIdx.x;
    int warp = tid >> 5, lane = tid & 31;
    int gid = lane >> 2, tig = lane & 3;
    int warp_m = (warp & 1) * 64;
    int warp_n = (warp >> 1) * 32;
    int bm = blockIdx.y * 128, bn = blockIdx.x * 128;

    float acc[4][4][4];
#pragma unroll
    for (int i = 0; i < 4; i++)
#pragma unroll
        for (int j = 0; j < 4; j++)
#pragma unroll
            for (int r = 0; r < 4; r++) acc[i][j][r] = 0.f;

    uint32_t as_base = (uint32_t)__cvta_generic_to_shared(&As[0][0]);
    uint32_t bs_base = (uint32_t)__cvta_generic_to_shared(&Bs[0][0]);

    int a_row = tid >> 2, a_kq = (tid & 3) * 4;  // A: rows a_row, a_row+64; k-quad a_kq
    int b_row = tid >> 5, b_nq = (tid & 31) * 4; // B: rows b_row, b_row+8; n-quad b_nq

    auto load_tiles = [&](int buf, int k0) {
        cp16(as_base + (uint32_t)(buf * 128 * SA + a_row * SA + a_kq) * 4u,
             &A[(size_t)(bm + a_row) * 256 + k0 + a_kq]);
        cp16(as_base + (uint32_t)(buf * 128 * SA + (a_row + 64) * SA + a_kq) * 4u,
             &A[(size_t)(bm + a_row + 64) * 256 + k0 + a_kq]);
        cp16(bs_base + (uint32_t)(buf * 16 * SB + b_row * SB + b_nq) * 4u,
             &B[(size_t)(k0 + b_row) * 256 + bn + b_nq]);
        cp16(bs_base + (uint32_t)(buf * 16 * SB + (b_row + 8) * SB + b_nq) * 4u,
             &B[(size_t)(k0 + b_row + 8) * 256 + bn + b_nq]);
    };

    load_tiles(0, 0);
    asm volatile("cp.async.commit_group;");

    for (int it = 0; it < 16; it++) {
        int buf = it & 1;
        if (it + 1 < 16) load_tiles(buf ^ 1, (it + 1) * 16);
        asm volatile("cp.async.commit_group;");
        asm volatile("cp.async.wait_group 1;");
        __syncthreads();

        const float* Ab = &As[buf][0];
        const float* Bb = &Bs[buf][0];
#pragma unroll
        for (int ks = 0; ks < 16; ks += 8) {
            uint32_t bfr[4][2];
#pragma unroll
            for (int fn = 0; fn < 4; fn++) {
                int n = warp_n + fn * 8 + gid;
                bfr[fn][0] = f2tf32(Bb[(ks + tig) * SB + n]);
                bfr[fn][1] = f2tf32(Bb[(ks + tig + 4) * SB + n]);
            }
            uint32_t afr[4][4];
#pragma unroll
            for (int fm = 0; fm < 4; fm++) {
                int m = warp_m + fm * 16 + gid;
                afr[fm][0] = f2tf32(Ab[m * SA + ks + tig]);
                afr[fm][1] = f2tf32(Ab[(m + 8) * SA + ks + tig]);
                afr[fm][2] = f2tf32(Ab[m * SA + ks + tig + 4]);
                afr[fm][3] = f2tf32(Ab[(m + 8) * SA + ks + tig + 4]);
            }
#pragma unroll
            for (int fm = 0; fm < 4; fm++)
#pragma unroll
                for (int fn = 0; fn < 4; fn++) mma8(acc[fm][fn], afr[fm], bfr[fn]);
        }
        __syncthreads();
    }

    // epilogue: add bias, store
#pragma unroll
    for (int fm = 0; fm < 4; fm++) {
        int row = bm + warp_m + fm * 16 + gid;
#pragma unroll
        for (int fn = 0; fn < 4; fn++) {
            int col = bn + warp_n + fn * 8 + tig * 2;
            float b0 = bias[col], b1 = bias[col + 1];
            float2 o0 = make_float2(acc[fm][fn][0] + b0, acc[fm][fn][1] + b1);
            float2 o1 = make_float2(acc[fm][fn][2] + b0, acc[fm][fn][3] + b1);
            *reinterpret_cast<float2*>(&Cm[(size_t)row * 256 + col]) = o0;
            *reinterpret_cast<float2*>(&Cm[(size_t)(row + 8) * 256 + col]) = o1;
        }
    }
}

// ------------------------- edge pass 1: alpha + exp + denom -------------------------
__global__ void edge_alpha_kernel(const int* __restrict__ src, const int* __restrict__ dst,
                                  const float* __restrict__ ea, const float* __restrict__ We) {
    __shared__ float sWe[256];
    int tid = threadIdx.x;
    sWe[tid] = We[tid];
    __syncthreads();
    int warp = tid >> 5, lane = tid & 31;
    int e = blockIdx.x * 8 + warp;
    if (e >= EE) return;
    int s = src[e], d = dst[e];
    float av = ea[e];
    int head = lane >> 3, sub = lane & 7;
    int ch = head * 64 + sub * 8;
    const float4* qp = reinterpret_cast<const float4*>(&g_q[d * 256 + ch]);
    const float4* kp = reinterpret_cast<const float4*>(&g_k[s * 256 + ch]);
    const float4* wp = reinterpret_cast<const float4*>(&sWe[ch]);
    float p = 0.f;
#pragma unroll
    for (int t = 0; t < 2; t++) {
        float4 q4 = qp[t], k4 = kp[t], w4 = wp[t];
        p += q4.x * (k4.x + av * w4.x) + q4.y * (k4.y + av * w4.y) +
             q4.z * (k4.z + av * w4.z) + q4.w * (k4.w + av * w4.w);
    }
    p += __shfl_down_sync(0xffffffffu, p, 4);
    p += __shfl_down_sync(0xffffffffu, p, 2);
    p += __shfl_down_sync(0xffffffffu, p, 1);
    if (sub == 0) {
        float ex = expf(p * 0.125f);  // scale = 1/sqrt(64); softmax max-shift cancels in the ratio
        g_exw[e * 4 + head] = ex;
        atomicAdd(&g_den[d * 4 + head], ex);
    }
}

// ------------------------- edge pass 2: weighted message scatter -------------------------
__global__ void edge_msg_kernel(const int* __restrict__ src, const int* __restrict__ dst,
                                const float* __restrict__ ea, const float* __restrict__ We) {
    __shared__ float sWe[256];
    int tid = threadIdx.x;
    sWe[tid] = We[tid];
    __syncthreads();
    int warp = tid >> 5, lane = tid & 31;
    int e = blockIdx.x * 8 + warp;
    if (e >= EE) return;
    int s = src[e], d = dst[e];
    float av = ea[e];
    int head = lane >> 3, sub = lane & 7;
    float w = g_exw[e * 4 + head] / g_den[d * 4 + head];
    int ch = head * 64 + sub * 8;
    const float4* vp = reinterpret_cast<const float4*>(&g_v[s * 256 + ch]);
    const float4* wp = reinterpret_cast<const float4*>(&sWe[ch]);
#pragma unroll
    for (int t = 0; t < 2; t++) {
        float4 v4 = vp[t], w4 = wp[t];
        float4 m;
        m.x = (v4.x + av * w4.x) * w;
        m.y = (v4.y + av * w4.y) * w;
        m.z = (v4.z + av * w4.z) * w;
        m.w = (v4.w + av * w4.w) * w;
        atomicAdd(reinterpret_cast<float4*>(&g_msg[d * 256 + ch + t * 4]), m);
    }
}

// ------------------------- beta-gated skip combine -------------------------
__global__ void combine_kernel(const float* __restrict__ Wb) {
    __shared__ float sWb[768];
    int tid = threadIdx.x;
    sWb[tid] = Wb[tid];
    sWb[tid + 256] = Wb[tid + 256];
    sWb[tid + 512] = Wb[tid + 512];
    __syncthreads();
    int warp = tid >> 5, lane = tid & 31;
    int n = blockIdx.x * 8 + warp;
    if (n >= NN) return;
    int ch = lane * 8;
    float4 o0 = *reinterpret_cast<const float4*>(&g_msg[n * 256 + ch]);
    float4 o1 = *reinterpret_cast<const float4*>(&g_msg[n * 256 + ch + 4]);
    float4 x0 = *reinterpret_cast<const float4*>(&g_xr[n * 256 + ch]);
    float4 x1 = *reinterpret_cast<const float4*>(&g_xr[n * 256 + ch + 4]);
    float ov[8] = {o0.x, o0.y, o0.z, o0.w, o1.x, o1.y, o1.z, o1.w};
    float xv[8] = {x0.x, x0.y, x0.z, x0.w, x1.x, x1.y, x1.z, x1.w};
    float p = 0.f;
#pragma unroll
    for (int i = 0; i < 8; i++)
        p += ov[i] * sWb[ch + i] + xv[i] * sWb[256 + ch + i] + (ov[i] - xv[i]) * sWb[512 + ch + i];
#pragma unroll
    for (int off = 16; off; off >>= 1) p += __shfl_xor_sync(0xffffffffu, p, off);
    float beta = 1.f / (1.f + expf(-p));
    float r[8];
#pragma unroll
    for (int i = 0; i < 8; i++) r[i] = beta * xv[i] + (1.f - beta) * ov[i];
    *reinterpret_cast<float4*>(&g_h[n * 256 + ch]) = make_float4(r[0], r[1], r[2], r[3]);
    *reinterpret_cast<float4*>(&g_h[n * 256 + ch + 4]) = make_float4(r[4], r[5], r[6], r[7]);
}

// ------------------------- batchnorm column stats -------------------------
__global__ void bn_reduce_kernel() {
    int d = threadIdx.x;
    int r0 = blockIdx.x * 128;
    float s = 0.f, s2 = 0.f;
    for (int r = 0; r < 128; r++) {
        float v = g_h[(r0 + r) * 256 + d];
        s += v;
        s2 += v * v;
    }
    atomicAdd(&g_colstats[d], s);
    atomicAdd(&g_colstats[256 + d], s2);
}

// ------------------------- BN apply + ELU -------------------------
__global__ void bn_apply_kernel(const float* __restrict__ gamma, const float* __restrict__ beta) {
    int i = blockIdx.x * blockDim.x + threadIdx.x;
    if (i >= NN * DD) return;
    int d = i & 255;
    float mu = g_colstats[d] * (1.f / NN);
    float var = g_colstats[256 + d] * (1.f / NN) - mu * mu;
    float y = gamma[d] * (g_h[i] - mu) * rsqrtf(var + BN_EPS) + beta[d];
    g_h[i] = y > 0.f ? y : expm1f(y);
}

// ------------------------- readout: gate softmax denom -------------------------
__global__ void gate_kernel(const int* __restrict__ batch, const float* __restrict__ gW,
                            const float* __restrict__ gb) {
    int tid = threadIdx.x;
    int warp = tid >> 5, lane = tid & 31;
    int n = blockIdx.x * 8 + warp;
    if (n >= NN) return;
    float p = 0.f;
#pragma unroll
    for (int t = 0; t < 8; t++) {
        int ch = lane + t * 32;
        p += g_h[n * 256 + ch] * gW[ch];
    }
#pragma unroll
    for (int off = 16; off; off >>= 1) p += __shfl_xor_sync(0xffffffffu, p, off);
    if (lane == 0) {
        float ex = expf(p + gb[0]);
        g_gate[n] = ex;
        atomicAdd(&g_gden[batch[n]], ex);
    }
}

// ------------------------- readout: weighted pooling -------------------------
__global__ void pool_kernel(const int* __restrict__ batch) {
    int i = blockIdx.x * blockDim.x + threadIdx.x;
    if (i >= NN * 64) return;
    int n = i >> 6, c4 = (i & 63) * 4;
    int g = batch[n];
    float w = g_gate[n] / g_gden[g];
    float4 hv = *reinterpret_cast<const float4*>(&g_h[n * 256 + c4]);
    float4 m = make_float4(hv.x * w, hv.y * w, hv.z * w, hv.w * w);
    atomicAdd(reinterpret_cast<float4*>(&g_hG[g * 256 + c4]), m);
}

// ------------------------- decoder -------------------------
__global__ void final_kernel(const float* __restrict__ dW, const float* __restrict__ db,
                             const float* __restrict__ ob, float* __restrict__ out) {
    __shared__ float red[256];
    int g = blockIdx.x, t = threadIdx.x;
    red[t] = g_hG[g * 256 + t] * dW[t];
    __syncthreads();
    for (int s = 128; s > 0; s >>= 1) {
        if (t < s) red[t] += red[t + s];
        __syncthreads();
    }
    if (t == 0) out[g] = red[0] + db[0] + ob[0];
}

// ------------------------- launcher -------------------------
extern "C" void kernel_launch(void* const* d_in, const int* in_sizes, int n_in,
                              void* d_out, int out_size) {
    const float* x     = (const float*)d_in[0];
    const int*   ei    = (const int*)d_in[1];
    const float* ea    = (const float*)d_in[2];
    const int*   batch = (const int*)d_in[3];
    const float* encW  = (const float*)d_in[4];
    const float* encb  = (const float*)d_in[5];
    const float* Wq    = (const float*)d_in[6];
    const float* bq    = (const float*)d_in[7];
    const float* Wk    = (const float*)d_in[8];
    const float* bk    = (const float*)d_in[9];
    const float* Wv    = (const float*)d_in[10];
    const float* bv    = (const float*)d_in[11];
    const float* We    = (const float*)d_in[12];
    const float* Wskip = (const float*)d_in[13];
    const float* bskip = (const float*)d_in[14];
    const float* Wbeta = (const float*)d_in[15];
    const float* bng   = (const float*)d_in[16];
    const float* bnb   = (const float*)d_in[17];
    const float* gW    = (const float*)d_in[18];
    const float* gb    = (const float*)d_in[19];
    const float* dW    = (const float*)d_in[20];
    const float* db    = (const float*)d_in[21];
    const float* ob    = (const float*)d_in[22];
    float* out = (float*)d_out;

    const int* src = ei;        // edge_index[0]
    const int* dst = ei + EE;   // edge_index[1]

    const int TPB = 256;
    const int ND_BLOCKS = (NN * DD) / TPB;          // 32768
    dim3 gemm_grid(2, 256);

    encoder_kernel<<<ND_BLOCKS, TPB>>>(x, encW, encb);

    for (int l = 0; l < 2; l++) {
        const float* Wq_l = Wq + (size_t)l * DD * DD;
        const float* Wk_l = Wk + (size_t)l * DD * DD;
        const float* Wv_l = Wv + (size_t)l * DD * DD;
        const float* Ws_l = Wskip + (size_t)l * DD * DD;
        mma_gemm_bias<<<gemm_grid, TPB>>>(Wq_l, bq + l * DD, 0);
        mma_gemm_bias<<<gemm_grid, TPB>>>(Wk_l, bk + l * DD, 1);
        mma_gemm_bias<<<gemm_grid, TPB>>>(Wv_l, bv + l * DD, 2);
        mma_gemm_bias<<<gemm_grid, TPB>>>(Ws_l, bskip + l * DD, 3);

        zero_layer_kernel<<<ND_BLOCKS, TPB>>>();

        edge_alpha_kernel<<<EE / 8, TPB>>>(src, dst, ea, We + l * DD);
        edge_msg_kernel<<<EE / 8, TPB>>>(src, dst, ea, We + l * DD);

        combine_kernel<<<NN / 8, TPB>>>(Wbeta + l * 3 * DD);
        bn_reduce_kernel<<<256, TPB>>>();
        bn_apply_kernel<<<ND_BLOCKS, TPB>>>(bng + l * DD, bnb + l * DD);
    }

    zero_readout_kernel<<<32, TPB>>>();
    gate_kernel<<<NN / 8, TPB>>>(batch, gW, gb);
    pool_kernel<<<(NN * 64) / TPB, TPB>>>(batch);
    final_kernel<<<GG, TPB>>>(dW, db, ob, out);
}